// round 15
// baseline (speedup 1.0000x reference)
#include <cuda_runtime.h>
#include <cuda_bf16.h>
#include <mma.h>
#include <cstdint>

using namespace nvcuda;

#define N_NODES 50000
#define E_EDGES 800000
#define INF_    256
#define OUTF_   32
#define HEADS_  8
#define HF_     256   // HEADS_ * OUTF_
#define MPAD    50048 // 391 * 128, padded row count for boundless stores

// ---------------- scratch (static __device__, no allocation) ----------------
__device__ __nv_bfloat16 g_wh[HF_ * INF_];               // W hi, [j=head*32+f][k]
__device__ __nv_bfloat16 g_wl[HF_ * INF_];               // W lo
__device__ float g_h[(size_t)MPAD * HF_];                // transformed features (padded)
__device__ float g_ssrc[N_NODES * HEADS_];
__device__ float g_sdst[N_NODES * HEADS_];
__device__ int   g_deg[N_NODES];
__device__ int   g_cursor[N_NODES];
__device__ int   g_rowstart[N_NODES + 1];
__device__ int   g_csr_src[E_EDGES];

// -------- W pack + bf16 split, fused with deg/cursor zeroing -----------------
__global__ void k_wsz(const float* __restrict__ W, int NN) {
    int idx = blockIdx.x * blockDim.x + threadIdx.x;     // idx = j*256 + k
    if (idx < NN) { g_deg[idx] = 0; g_cursor[idx] = 0; }
    if (idx >= HF_ * INF_) return;
    int j = idx >> 8;
    int k = idx & 255;
    int head = j >> 5;
    int f = j & 31;
    float w = W[head * (INF_ * OUTF_) + k * OUTF_ + f];
    __nv_bfloat16 hi = __float2bfloat16(w);
    float r = w - __bfloat162float(hi);
    g_wh[idx] = hi;
    g_wl[idx] = __float2bfloat16(r);
}

// ---------------- WMMA bf16-split GEMM + fused score epilogue ----------------
// CTA 128x128, 8 warps (4 row x 2 col), warp tile 32x64 = 2x4 m16n16k16 frags.
// acc += ah*bh + ah*bl + al*bh  (al*bl ~2^-18 dropped). x split fp32->hi/lo in
// registers during the smem stage; h stores go unguarded into padded g_h.
// Epilogue: s_src/s_dst from the CTA's just-stored h rows (L1-hot).
#define LDA 40   // padded smem leading dim (elements); conflict-free for LDSM
__global__ void __launch_bounds__(256, 2) k_gemm_wmma(const float* __restrict__ x,
                                                      const float* __restrict__ a_src,
                                                      const float* __restrict__ a_dst,
                                                      int M) {
    __shared__ __nv_bfloat16 Ah[128 * LDA], Al[128 * LDA];
    __shared__ __nv_bfloat16 Bh[128 * LDA], Bl[128 * LDA];
    const int tid = threadIdx.x;
    const int warp = tid >> 5;
    const int wm = warp & 3;
    const int wn = warp >> 2;
    const int m0 = blockIdx.y * 128;
    const int n0 = blockIdx.x * 128;

    wmma::fragment<wmma::accumulator, 16, 16, 16, float> acc[2][4];
#pragma unroll
    for (int i = 0; i < 2; i++)
#pragma unroll
        for (int j = 0; j < 4; j++) wmma::fill_fragment(acc[i][j], 0.f);

    for (int k0 = 0; k0 < INF_; k0 += 32) {
        __syncthreads();
#pragma unroll
        for (int u = 0; u < 2; u++) {
            int id = tid + u * 256;          // 0..511
            int row = id >> 2;               // 0..127
            int c8 = (id & 3) * 8;           // col in elements
            // A: load fp32 x, split to bf16 hi/lo in-register
            float4 v0 = make_float4(0.f, 0.f, 0.f, 0.f), v1 = v0;
            if (m0 + row < M) {
                const float* xp = &x[(size_t)(m0 + row) * INF_ + k0 + c8];
                v0 = *(const float4*)xp;
                v1 = *(const float4*)(xp + 4);
            }
            float v[8] = {v0.x, v0.y, v0.z, v0.w, v1.x, v1.y, v1.z, v1.w};
            uint32_t hp[4], lp[4];
#pragma unroll
            for (int q = 0; q < 4; q++) {
                __nv_bfloat16 h0 = __float2bfloat16(v[2 * q]);
                __nv_bfloat16 h1 = __float2bfloat16(v[2 * q + 1]);
                float r0 = v[2 * q] - __bfloat162float(h0);
                float r1 = v[2 * q + 1] - __bfloat162float(h1);
                hp[q] = (uint32_t)__bfloat16_as_ushort(h0) |
                        ((uint32_t)__bfloat16_as_ushort(h1) << 16);
                lp[q] = (uint32_t)__bfloat16_as_ushort(__float2bfloat16(r0)) |
                        ((uint32_t)__bfloat16_as_ushort(__float2bfloat16(r1)) << 16);
            }
            *(uint4*)&Ah[row * LDA + c8] = make_uint4(hp[0], hp[1], hp[2], hp[3]);
            *(uint4*)&Al[row * LDA + c8] = make_uint4(lp[0], lp[1], lp[2], lp[3]);
            // B: straight bf16 copy (pre-split)
            size_t gb = (size_t)(n0 + row) * INF_ + k0 + c8;
            *(uint4*)&Bh[row * LDA + c8] = *(const uint4*)&g_wh[gb];
            *(uint4*)&Bl[row * LDA + c8] = *(const uint4*)&g_wl[gb];
        }
        __syncthreads();

#pragma unroll
        for (int ks = 0; ks < 2; ks++) {
            wmma::fragment<wmma::matrix_a, 16, 16, 16, __nv_bfloat16, wmma::row_major> ah[2], al[2];
#pragma unroll
            for (int i = 0; i < 2; i++) {
                int ro = (wm * 32 + i * 16) * LDA + ks * 16;
                wmma::load_matrix_sync(ah[i], &Ah[ro], LDA);
                wmma::load_matrix_sync(al[i], &Al[ro], LDA);
            }
#pragma unroll
            for (int j = 0; j < 4; j++) {
                wmma::fragment<wmma::matrix_b, 16, 16, 16, __nv_bfloat16, wmma::col_major> bh, bl;
                int ro = (wn * 64 + j * 16) * LDA + ks * 16;
                wmma::load_matrix_sync(bh, &Bh[ro], LDA);
                wmma::load_matrix_sync(bl, &Bl[ro], LDA);
#pragma unroll
                for (int i = 0; i < 2; i++) {
                    wmma::mma_sync(acc[i][j], ah[i], bh, acc[i][j]);
                    wmma::mma_sync(acc[i][j], ah[i], bl, acc[i][j]);
                    wmma::mma_sync(acc[i][j], al[i], bh, acc[i][j]);
                }
            }
        }
    }

    // stores unguarded into padded g_h (MPAD rows)
#pragma unroll
    for (int i = 0; i < 2; i++)
#pragma unroll
        for (int j = 0; j < 4; j++)
            wmma::store_matrix_sync(
                &g_h[(size_t)(m0 + wm * 32 + 16 * i) * HF_ + n0 + wn * 64 + 16 * j],
                acc[i][j], HF_, wmma::mem_row_major);

    // ---- fused score epilogue: block-scope visibility of our own g_h stores
    __syncthreads();
    {
        const int r = tid >> 1;               // 0..127
        const int half = tid & 1;             // 0..1
        const int row = m0 + r;
        if (row < M) {
            const int c0 = n0 + half * 64;    // 2 heads' columns
            const int hbase = c0 >> 5;        // first head index
            const float* hp = &g_h[(size_t)row * HF_ + c0];
            float s0 = 0.f, d0 = 0.f, s1 = 0.f, d1 = 0.f;
#pragma unroll
            for (int q = 0; q < 8; q++) {
                float4 hv0 = *(const float4*)&hp[q * 4];
                float4 hv1 = *(const float4*)&hp[32 + q * 4];
                float4 a0 = *(const float4*)&a_src[hbase * 32 + q * 4];
                float4 b0 = *(const float4*)&a_dst[hbase * 32 + q * 4];
                float4 a1 = *(const float4*)&a_src[(hbase + 1) * 32 + q * 4];
                float4 b1 = *(const float4*)&a_dst[(hbase + 1) * 32 + q * 4];
                s0 += hv0.x * a0.x + hv0.y * a0.y + hv0.z * a0.z + hv0.w * a0.w;
                d0 += hv0.x * b0.x + hv0.y * b0.y + hv0.z * b0.z + hv0.w * b0.w;
                s1 += hv1.x * a1.x + hv1.y * a1.y + hv1.z * a1.z + hv1.w * a1.w;
                d1 += hv1.x * b1.x + hv1.y * b1.y + hv1.z * b1.z + hv1.w * b1.w;
            }
            g_ssrc[row * HEADS_ + hbase] = s0;
            g_ssrc[row * HEADS_ + hbase + 1] = s1;
            g_sdst[row * HEADS_ + hbase] = d0;
            g_sdst[row * HEADS_ + hbase + 1] = d1;
        }
    }
}

// ---------------- CSR build --------------------------------------------------
__global__ void k_count(const int* __restrict__ dst, int E) {
    int e = blockIdx.x * blockDim.x + threadIdx.x;
    if (e < E) atomicAdd(&g_deg[dst[e]], 1);
}

// single-block shfl scan, 4 elements per thread -> g_rowstart
__global__ void k_scan(int NN) {
    __shared__ int warpsum[32];
    __shared__ int carry;
    const int tid = threadIdx.x;
    const int lane = tid & 31;
    const int wid = tid >> 5;
    if (tid == 0) carry = 0;
    __syncthreads();
    for (int base = 0; base < NN; base += 4096) {
        int i0 = base + tid * 4;
        int v0 = (i0 + 0 < NN) ? g_deg[i0 + 0] : 0;
        int v1 = (i0 + 1 < NN) ? g_deg[i0 + 1] : 0;
        int v2 = (i0 + 2 < NN) ? g_deg[i0 + 2] : 0;
        int v3 = (i0 + 3 < NN) ? g_deg[i0 + 3] : 0;
        int tsum = v0 + v1 + v2 + v3;
        int s = tsum;
#pragma unroll
        for (int o = 1; o < 32; o <<= 1) {
            int t = __shfl_up_sync(0xffffffffu, s, o);
            if (lane >= o) s += t;
        }
        if (lane == 31) warpsum[wid] = s;
        __syncthreads();
        if (wid == 0) {
            int ws = warpsum[lane];
#pragma unroll
            for (int o = 1; o < 32; o <<= 1) {
                int t = __shfl_up_sync(0xffffffffu, ws, o);
                if (lane >= o) ws += t;
            }
            warpsum[lane] = ws;
        }
        __syncthreads();
        int excl = s - tsum + (wid > 0 ? warpsum[wid - 1] : 0) + carry;
        if (i0 + 0 < NN) g_rowstart[i0 + 0] = excl; excl += v0;
        if (i0 + 1 < NN) g_rowstart[i0 + 1] = excl; excl += v1;
        if (i0 + 2 < NN) g_rowstart[i0 + 2] = excl; excl += v2;
        if (i0 + 3 < NN) g_rowstart[i0 + 3] = excl;
        int total = warpsum[31];
        __syncthreads();
        if (tid == 0) carry += total;
        __syncthreads();
    }
    if (tid == 0) g_rowstart[NN] = carry;
}

__global__ void k_fill(const int* __restrict__ src, const int* __restrict__ dst, int E) {
    int e = blockIdx.x * blockDim.x + threadIdx.x;
    if (e >= E) return;
    int d = dst[e];
    int pos = atomicAdd(&g_cursor[d], 1);
    g_csr_src[g_rowstart[d] + pos] = src[e];
}

// ---------------- fused single-pass softmax + aggregation --------------------
// 2 nodes per 512-thread block, warp per (node,head), lane per output feature.
// Software-pipelined 8-edge batches: batch b+1's loads issue while batch b
// computes, overlapping consecutive L2-latency chains.
__global__ void __launch_bounds__(512) k_aggr(float* __restrict__ out, int NN) {
    const int n = blockIdx.x * 2 + (threadIdx.x >> 8);
    if (n >= NN) return;
    const int head = (threadIdx.x >> 5) & 7;
    const int lane = threadIdx.x & 31;
    const int rs = g_rowstart[n];
    const int re = g_rowstart[n + 1];
    const float sd = g_sdst[n * HEADS_ + head];
    const size_t hoff = head * OUTF_ + lane;

    float acc = 0.f, wsum = 0.f;
    int i = rs;
    const int nb = (re - rs) >> 3;
    if (nb > 0) {
        int sn[8];
        float an[8], hn[8];
#pragma unroll
        for (int q = 0; q < 8; q++) sn[q] = g_csr_src[i + q];
#pragma unroll
        for (int q = 0; q < 8; q++) an[q] = g_ssrc[sn[q] * HEADS_ + head];
#pragma unroll
        for (int q = 0; q < 8; q++) hn[q] = g_h[(size_t)sn[q] * HF_ + hoff];
        for (int b = 1; b < nb; b++) {
            int sn2[8];
            float an2[8], hn2[8];
#pragma unroll
            for (int q = 0; q < 8; q++) sn2[q] = g_csr_src[i + 8 + q];
#pragma unroll
            for (int q = 0; q < 8; q++) an2[q] = g_ssrc[sn2[q] * HEADS_ + head];
#pragma unroll
            for (int q = 0; q < 8; q++) hn2[q] = g_h[(size_t)sn2[q] * HF_ + hoff];
#pragma unroll
            for (int q = 0; q < 8; q++) {
                float a = an[q] + sd;
                a = a > 0.f ? a : 0.2f * a;
                float e = __expf(a);
                wsum += e;
                acc = fmaf(e, hn[q], acc);
            }
#pragma unroll
            for (int q = 0; q < 8; q++) { sn[q] = sn2[q]; an[q] = an2[q]; hn[q] = hn2[q]; }
            i += 8;
        }
#pragma unroll
        for (int q = 0; q < 8; q++) {
            float a = an[q] + sd;
            a = a > 0.f ? a : 0.2f * a;
            float e = __expf(a);
            wsum += e;
            acc = fmaf(e, hn[q], acc);
        }
        i += 8;
    }
    for (; i < re; i++) {
        int s = g_csr_src[i];
        float ea = g_ssrc[s * HEADS_ + head] + sd;
        ea = ea > 0.f ? ea : 0.2f * ea;
        float e = __expf(ea);
        wsum += e;
        acc = fmaf(e, g_h[(size_t)s * HF_ + hoff], acc);
    }
    out[(size_t)n * HF_ + head * OUTF_ + lane] = acc / (wsum + 1e-8f);
}

// ---------------- launch -----------------------------------------------------
// Order puts k_gemm_wmma at launch slot #4 (the slot ncu's -s5-c1 captures).
extern "C" void kernel_launch(void* const* d_in, const int* in_sizes, int n_in,
                              void* d_out, int out_size) {
    const float* x     = (const float*)d_in[0];
    const int*   ei    = (const int*)d_in[1];
    const float* W     = (const float*)d_in[2];
    const float* a_src = (const float*)d_in[3];
    const float* a_dst = (const float*)d_in[4];
    float* out = (float*)d_out;

    const int M = in_sizes[0] / INF_;     // 50000
    const int E = in_sizes[1] / 2;        // 800000
    const int* src = ei;
    const int* dst = ei + E;

    const int mblocks = (M + 127) / 128;  // 391; mblocks*128 <= MPAD

    k_wsz<<<(HF_ * INF_ + 255) / 256, 256>>>(W, M);
    k_count<<<(E + 255) / 256, 256>>>(dst, E);
    k_scan<<<1, 1024>>>(M);
    k_gemm_wmma<<<dim3(2, mblocks), 256>>>(x, a_src, a_dst, M);
    k_fill<<<(E + 255) / 256, 256>>>(src, dst, E);
    k_aggr<<<(M + 1) / 2, 512>>>(out, M);
}

// round 16
// speedup vs baseline: 1.2634x; 1.2634x over previous
#include <cuda_runtime.h>
#include <cuda_bf16.h>
#include <mma.h>
#include <cstdint>

using namespace nvcuda;

#define N_NODES 50000
#define E_EDGES 800000
#define INF_    256
#define OUTF_   32
#define HEADS_  8
#define HF_     256   // HEADS_ * OUTF_
#define MPAD    50048 // 391 * 128, padded row count for boundless stores

// ---------------- scratch (static __device__, no allocation) ----------------
__device__ __nv_bfloat16 g_wh[HF_ * INF_];               // W hi, [j=head*32+f][k]
__device__ __nv_bfloat16 g_wl[HF_ * INF_];               // W lo
__device__ float g_h[(size_t)MPAD * HF_];                // transformed features (padded)
__device__ float g_ssrc[N_NODES * HEADS_];
__device__ float g_sdst[N_NODES * HEADS_];
__device__ int   g_deg[N_NODES];
__device__ int   g_cursor[N_NODES];
__device__ int   g_rowstart[N_NODES + 1];
__device__ int   g_csr_src[E_EDGES];

// -------- W pack + bf16 split, fused with deg/cursor zeroing -----------------
__global__ void k_wsz(const float* __restrict__ W, int NN) {
    int idx = blockIdx.x * blockDim.x + threadIdx.x;     // idx = j*256 + k
    if (idx < NN) { g_deg[idx] = 0; g_cursor[idx] = 0; }
    if (idx >= HF_ * INF_) return;
    int j = idx >> 8;
    int k = idx & 255;
    int head = j >> 5;
    int f = j & 31;
    float w = W[head * (INF_ * OUTF_) + k * OUTF_ + f];
    __nv_bfloat16 hi = __float2bfloat16(w);
    float r = w - __bfloat162float(hi);
    g_wh[idx] = hi;
    g_wl[idx] = __float2bfloat16(r);
}

// ---------------- WMMA bf16-split GEMM + fused score epilogue ----------------
// CTA 128x128, 8 warps (4 row x 2 col), warp tile 32x64 = 2x4 m16n16k16 frags.
// acc += ah*bh + ah*bl + al*bh  (al*bl ~2^-18 dropped). x split fp32->hi/lo in
// registers during the smem stage; h stores go unguarded into padded g_h.
// Epilogue: s_src/s_dst from the CTA's just-stored h rows (L1-hot).
#define LDA 40   // padded smem leading dim (elements); conflict-free for LDSM
__global__ void __launch_bounds__(256, 2) k_gemm_wmma(const float* __restrict__ x,
                                                      const float* __restrict__ a_src,
                                                      const float* __restrict__ a_dst,
                                                      int M) {
    __shared__ __nv_bfloat16 Ah[128 * LDA], Al[128 * LDA];
    __shared__ __nv_bfloat16 Bh[128 * LDA], Bl[128 * LDA];
    const int tid = threadIdx.x;
    const int warp = tid >> 5;
    const int wm = warp & 3;
    const int wn = warp >> 2;
    const int m0 = blockIdx.y * 128;
    const int n0 = blockIdx.x * 128;

    wmma::fragment<wmma::accumulator, 16, 16, 16, float> acc[2][4];
#pragma unroll
    for (int i = 0; i < 2; i++)
#pragma unroll
        for (int j = 0; j < 4; j++) wmma::fill_fragment(acc[i][j], 0.f);

    for (int k0 = 0; k0 < INF_; k0 += 32) {
        __syncthreads();
#pragma unroll
        for (int u = 0; u < 2; u++) {
            int id = tid + u * 256;          // 0..511
            int row = id >> 2;               // 0..127
            int c8 = (id & 3) * 8;           // col in elements
            // A: load fp32 x, split to bf16 hi/lo in-register
            float4 v0 = make_float4(0.f, 0.f, 0.f, 0.f), v1 = v0;
            if (m0 + row < M) {
                const float* xp = &x[(size_t)(m0 + row) * INF_ + k0 + c8];
                v0 = *(const float4*)xp;
                v1 = *(const float4*)(xp + 4);
            }
            float v[8] = {v0.x, v0.y, v0.z, v0.w, v1.x, v1.y, v1.z, v1.w};
            uint32_t hp[4], lp[4];
#pragma unroll
            for (int q = 0; q < 4; q++) {
                __nv_bfloat16 h0 = __float2bfloat16(v[2 * q]);
                __nv_bfloat16 h1 = __float2bfloat16(v[2 * q + 1]);
                float r0 = v[2 * q] - __bfloat162float(h0);
                float r1 = v[2 * q + 1] - __bfloat162float(h1);
                hp[q] = (uint32_t)__bfloat16_as_ushort(h0) |
                        ((uint32_t)__bfloat16_as_ushort(h1) << 16);
                lp[q] = (uint32_t)__bfloat16_as_ushort(__float2bfloat16(r0)) |
                        ((uint32_t)__bfloat16_as_ushort(__float2bfloat16(r1)) << 16);
            }
            *(uint4*)&Ah[row * LDA + c8] = make_uint4(hp[0], hp[1], hp[2], hp[3]);
            *(uint4*)&Al[row * LDA + c8] = make_uint4(lp[0], lp[1], lp[2], lp[3]);
            // B: straight bf16 copy (pre-split)
            size_t gb = (size_t)(n0 + row) * INF_ + k0 + c8;
            *(uint4*)&Bh[row * LDA + c8] = *(const uint4*)&g_wh[gb];
            *(uint4*)&Bl[row * LDA + c8] = *(const uint4*)&g_wl[gb];
        }
        __syncthreads();

#pragma unroll
        for (int ks = 0; ks < 2; ks++) {
            wmma::fragment<wmma::matrix_a, 16, 16, 16, __nv_bfloat16, wmma::row_major> ah[2], al[2];
#pragma unroll
            for (int i = 0; i < 2; i++) {
                int ro = (wm * 32 + i * 16) * LDA + ks * 16;
                wmma::load_matrix_sync(ah[i], &Ah[ro], LDA);
                wmma::load_matrix_sync(al[i], &Al[ro], LDA);
            }
#pragma unroll
            for (int j = 0; j < 4; j++) {
                wmma::fragment<wmma::matrix_b, 16, 16, 16, __nv_bfloat16, wmma::col_major> bh, bl;
                int ro = (wn * 64 + j * 16) * LDA + ks * 16;
                wmma::load_matrix_sync(bh, &Bh[ro], LDA);
                wmma::load_matrix_sync(bl, &Bl[ro], LDA);
#pragma unroll
                for (int i = 0; i < 2; i++) {
                    wmma::mma_sync(acc[i][j], ah[i], bh, acc[i][j]);
                    wmma::mma_sync(acc[i][j], ah[i], bl, acc[i][j]);
                    wmma::mma_sync(acc[i][j], al[i], bh, acc[i][j]);
                }
            }
        }
    }

    // stores unguarded into padded g_h (MPAD rows)
#pragma unroll
    for (int i = 0; i < 2; i++)
#pragma unroll
        for (int j = 0; j < 4; j++)
            wmma::store_matrix_sync(
                &g_h[(size_t)(m0 + wm * 32 + 16 * i) * HF_ + n0 + wn * 64 + 16 * j],
                acc[i][j], HF_, wmma::mem_row_major);

    // ---- fused score epilogue: block-scope visibility of our own g_h stores
    __syncthreads();
    {
        const int r = tid >> 1;               // 0..127
        const int half = tid & 1;             // 0..1
        const int row = m0 + r;
        if (row < M) {
            const int c0 = n0 + half * 64;    // 2 heads' columns
            const int hbase = c0 >> 5;        // first head index
            const float* hp = &g_h[(size_t)row * HF_ + c0];
            float s0 = 0.f, d0 = 0.f, s1 = 0.f, d1 = 0.f;
#pragma unroll
            for (int q = 0; q < 8; q++) {
                float4 hv0 = *(const float4*)&hp[q * 4];
                float4 hv1 = *(const float4*)&hp[32 + q * 4];
                float4 a0 = *(const float4*)&a_src[hbase * 32 + q * 4];
                float4 b0 = *(const float4*)&a_dst[hbase * 32 + q * 4];
                float4 a1 = *(const float4*)&a_src[(hbase + 1) * 32 + q * 4];
                float4 b1 = *(const float4*)&a_dst[(hbase + 1) * 32 + q * 4];
                s0 += hv0.x * a0.x + hv0.y * a0.y + hv0.z * a0.z + hv0.w * a0.w;
                d0 += hv0.x * b0.x + hv0.y * b0.y + hv0.z * b0.z + hv0.w * b0.w;
                s1 += hv1.x * a1.x + hv1.y * a1.y + hv1.z * a1.z + hv1.w * a1.w;
                d1 += hv1.x * b1.x + hv1.y * b1.y + hv1.z * b1.z + hv1.w * b1.w;
            }
            g_ssrc[row * HEADS_ + hbase] = s0;
            g_ssrc[row * HEADS_ + hbase + 1] = s1;
            g_sdst[row * HEADS_ + hbase] = d0;
            g_sdst[row * HEADS_ + hbase + 1] = d1;
        }
    }
}

// ---------------- CSR build --------------------------------------------------
__global__ void k_count(const int* __restrict__ dst, int E) {
    int e = blockIdx.x * blockDim.x + threadIdx.x;
    if (e < E) atomicAdd(&g_deg[dst[e]], 1);
}

// single-block shfl scan, 4 elements per thread -> g_rowstart
__global__ void k_scan(int NN) {
    __shared__ int warpsum[32];
    __shared__ int carry;
    const int tid = threadIdx.x;
    const int lane = tid & 31;
    const int wid = tid >> 5;
    if (tid == 0) carry = 0;
    __syncthreads();
    for (int base = 0; base < NN; base += 4096) {
        int i0 = base + tid * 4;
        int v0 = (i0 + 0 < NN) ? g_deg[i0 + 0] : 0;
        int v1 = (i0 + 1 < NN) ? g_deg[i0 + 1] : 0;
        int v2 = (i0 + 2 < NN) ? g_deg[i0 + 2] : 0;
        int v3 = (i0 + 3 < NN) ? g_deg[i0 + 3] : 0;
        int tsum = v0 + v1 + v2 + v3;
        int s = tsum;
#pragma unroll
        for (int o = 1; o < 32; o <<= 1) {
            int t = __shfl_up_sync(0xffffffffu, s, o);
            if (lane >= o) s += t;
        }
        if (lane == 31) warpsum[wid] = s;
        __syncthreads();
        if (wid == 0) {
            int ws = warpsum[lane];
#pragma unroll
            for (int o = 1; o < 32; o <<= 1) {
                int t = __shfl_up_sync(0xffffffffu, ws, o);
                if (lane >= o) ws += t;
            }
            warpsum[lane] = ws;
        }
        __syncthreads();
        int excl = s - tsum + (wid > 0 ? warpsum[wid - 1] : 0) + carry;
        if (i0 + 0 < NN) g_rowstart[i0 + 0] = excl; excl += v0;
        if (i0 + 1 < NN) g_rowstart[i0 + 1] = excl; excl += v1;
        if (i0 + 2 < NN) g_rowstart[i0 + 2] = excl; excl += v2;
        if (i0 + 3 < NN) g_rowstart[i0 + 3] = excl;
        int total = warpsum[31];
        __syncthreads();
        if (tid == 0) carry += total;
        __syncthreads();
    }
    if (tid == 0) g_rowstart[NN] = carry;
}

__global__ void k_fill(const int* __restrict__ src, const int* __restrict__ dst, int E) {
    int e = blockIdx.x * blockDim.x + threadIdx.x;
    if (e >= E) return;
    int d = dst[e];
    int pos = atomicAdd(&g_cursor[d], 1);
    g_csr_src[g_rowstart[d] + pos] = src[e];
}

// ---------------- fused single-pass softmax + aggregation --------------------
// One node per 256-thread block, warp per head, lane per output feature.
// Per 64-edge chunk: indices + all-heads scores staged cooperatively in smem
// (scores fetched ONCE per edge as a coalesced 32B sector instead of 8 per-head
// 4B gathers). Warps then read scores via LDS and gather h rows unroll-8.
#define CHUNK 64
__global__ void __launch_bounds__(256) k_aggr(float* __restrict__ out, int NN) {
    __shared__ int   s_idx[CHUNK];
    __shared__ float s_sc[CHUNK * HEADS_];
    const int n = blockIdx.x;
    const int tid = threadIdx.x;
    const int head = tid >> 5;
    const int lane = tid & 31;
    const int rs = g_rowstart[n];
    const int re = g_rowstart[n + 1];
    const float sd = g_sdst[n * HEADS_ + head];
    const size_t hoff = head * OUTF_ + lane;

    float acc = 0.f, wsum = 0.f;
    for (int base = rs; base < re; base += CHUNK) {
        const int cnt = min(CHUNK, re - base);
        __syncthreads();                       // s_idx/s_sc reuse safety
        if (tid < cnt) s_idx[tid] = g_csr_src[base + tid];
        __syncthreads();
        for (int t = tid; t < cnt * HEADS_; t += 256)
            s_sc[t] = g_ssrc[s_idx[t >> 3] * HEADS_ + (t & 7)];
        __syncthreads();

        int j = 0;
        for (; j + 8 <= cnt; j += 8) {
            float hn[8];
#pragma unroll
            for (int q = 0; q < 8; q++)
                hn[q] = g_h[(size_t)s_idx[j + q] * HF_ + hoff];
#pragma unroll
            for (int q = 0; q < 8; q++) {
                float a = s_sc[(j + q) * HEADS_ + head] + sd;
                a = a > 0.f ? a : 0.2f * a;
                float e = __expf(a);
                wsum += e;
                acc = fmaf(e, hn[q], acc);
            }
        }
        for (; j < cnt; j++) {
            float h = g_h[(size_t)s_idx[j] * HF_ + hoff];
            float a = s_sc[j * HEADS_ + head] + sd;
            a = a > 0.f ? a : 0.2f * a;
            float e = __expf(a);
            wsum += e;
            acc = fmaf(e, h, acc);
        }
    }
    out[(size_t)n * HF_ + head * OUTF_ + lane] = acc / (wsum + 1e-8f);
}

// ---------------- launch -----------------------------------------------------
extern "C" void kernel_launch(void* const* d_in, const int* in_sizes, int n_in,
                              void* d_out, int out_size) {
    const float* x     = (const float*)d_in[0];
    const int*   ei    = (const int*)d_in[1];
    const float* W     = (const float*)d_in[2];
    const float* a_src = (const float*)d_in[3];
    const float* a_dst = (const float*)d_in[4];
    float* out = (float*)d_out;

    const int M = in_sizes[0] / INF_;     // 50000
    const int E = in_sizes[1] / 2;        // 800000
    const int* src = ei;
    const int* dst = ei + E;

    const int mblocks = (M + 127) / 128;  // 391; mblocks*128 <= MPAD

    k_wsz<<<(HF_ * INF_ + 255) / 256, 256>>>(W, M);
    k_count<<<(E + 255) / 256, 256>>>(dst, E);
    k_scan<<<1, 1024>>>(M);
    k_gemm_wmma<<<dim3(2, mblocks), 256>>>(x, a_src, a_dst, M);
    k_fill<<<(E + 255) / 256, 256>>>(src, dst, E);
    k_aggr<<<M, 256>>>(out, M);
}

// round 17
// speedup vs baseline: 1.8931x; 1.4984x over previous
#include <cuda_runtime.h>
#include <cuda_bf16.h>
#include <mma.h>
#include <cstdint>

using namespace nvcuda;

#define N_NODES 50000
#define E_EDGES 800000
#define INF_    256
#define OUTF_   32
#define HEADS_  8
#define HF_     256   // HEADS_ * OUTF_
#define MPAD    50048 // 391 * 128, padded row count for boundless stores

// ---------------- scratch (static __device__, no allocation) ----------------
__device__ __nv_bfloat16 g_wh[HF_ * INF_];               // W hi, [j=head*32+f][k]
__device__ __nv_bfloat16 g_wl[HF_ * INF_];               // W lo
__device__ float g_h[(size_t)MPAD * HF_];                // transformed features (padded)
__device__ float g_ssrc[N_NODES * HEADS_];
__device__ float g_sdst[N_NODES * HEADS_];
__device__ int   g_deg[N_NODES];
__device__ int   g_cursor[N_NODES];
__device__ int   g_rowstart[N_NODES + 1];
__device__ int   g_csr_src[E_EDGES];

// -------- W pack + bf16 split, fused with deg/cursor zeroing -----------------
__global__ void k_wsz(const float* __restrict__ W, int NN) {
    int idx = blockIdx.x * blockDim.x + threadIdx.x;     // idx = j*256 + k
    if (idx < NN) { g_deg[idx] = 0; g_cursor[idx] = 0; }
    if (idx >= HF_ * INF_) return;
    int j = idx >> 8;
    int k = idx & 255;
    int head = j >> 5;
    int f = j & 31;
    float w = W[head * (INF_ * OUTF_) + k * OUTF_ + f];
    __nv_bfloat16 hi = __float2bfloat16(w);
    float r = w - __bfloat162float(hi);
    g_wh[idx] = hi;
    g_wl[idx] = __float2bfloat16(r);
}

// ---------------- WMMA bf16-split GEMM + fused score epilogue ----------------
// CTA 128x128, 8 warps (4 row x 2 col), warp tile 32x64 = 2x4 m16n16k16 frags.
// acc += ah*bh + ah*bl + al*bh  (al*bl ~2^-18 dropped). x split fp32->hi/lo in
// registers during the smem stage; h stores go unguarded into padded g_h.
// Epilogue: s_src/s_dst from the CTA's just-stored h rows (L1-hot).
#define LDA 40   // padded smem leading dim (elements); conflict-free for LDSM
__global__ void __launch_bounds__(256, 2) k_gemm_wmma(const float* __restrict__ x,
                                                      const float* __restrict__ a_src,
                                                      const float* __restrict__ a_dst,
                                                      int M) {
    __shared__ __nv_bfloat16 Ah[128 * LDA], Al[128 * LDA];
    __shared__ __nv_bfloat16 Bh[128 * LDA], Bl[128 * LDA];
    const int tid = threadIdx.x;
    const int warp = tid >> 5;
    const int wm = warp & 3;
    const int wn = warp >> 2;
    const int m0 = blockIdx.y * 128;
    const int n0 = blockIdx.x * 128;

    wmma::fragment<wmma::accumulator, 16, 16, 16, float> acc[2][4];
#pragma unroll
    for (int i = 0; i < 2; i++)
#pragma unroll
        for (int j = 0; j < 4; j++) wmma::fill_fragment(acc[i][j], 0.f);

    for (int k0 = 0; k0 < INF_; k0 += 32) {
        __syncthreads();
#pragma unroll
        for (int u = 0; u < 2; u++) {
            int id = tid + u * 256;          // 0..511
            int row = id >> 2;               // 0..127
            int c8 = (id & 3) * 8;           // col in elements
            // A: load fp32 x, split to bf16 hi/lo in-register
            float4 v0 = make_float4(0.f, 0.f, 0.f, 0.f), v1 = v0;
            if (m0 + row < M) {
                const float* xp = &x[(size_t)(m0 + row) * INF_ + k0 + c8];
                v0 = *(const float4*)xp;
                v1 = *(const float4*)(xp + 4);
            }
            float v[8] = {v0.x, v0.y, v0.z, v0.w, v1.x, v1.y, v1.z, v1.w};
            uint32_t hp[4], lp[4];
#pragma unroll
            for (int q = 0; q < 4; q++) {
                __nv_bfloat16 h0 = __float2bfloat16(v[2 * q]);
                __nv_bfloat16 h1 = __float2bfloat16(v[2 * q + 1]);
                float r0 = v[2 * q] - __bfloat162float(h0);
                float r1 = v[2 * q + 1] - __bfloat162float(h1);
                hp[q] = (uint32_t)__bfloat16_as_ushort(h0) |
                        ((uint32_t)__bfloat16_as_ushort(h1) << 16);
                lp[q] = (uint32_t)__bfloat16_as_ushort(__float2bfloat16(r0)) |
                        ((uint32_t)__bfloat16_as_ushort(__float2bfloat16(r1)) << 16);
            }
            *(uint4*)&Ah[row * LDA + c8] = make_uint4(hp[0], hp[1], hp[2], hp[3]);
            *(uint4*)&Al[row * LDA + c8] = make_uint4(lp[0], lp[1], lp[2], lp[3]);
            // B: straight bf16 copy (pre-split)
            size_t gb = (size_t)(n0 + row) * INF_ + k0 + c8;
            *(uint4*)&Bh[row * LDA + c8] = *(const uint4*)&g_wh[gb];
            *(uint4*)&Bl[row * LDA + c8] = *(const uint4*)&g_wl[gb];
        }
        __syncthreads();

#pragma unroll
        for (int ks = 0; ks < 2; ks++) {
            wmma::fragment<wmma::matrix_a, 16, 16, 16, __nv_bfloat16, wmma::row_major> ah[2], al[2];
#pragma unroll
            for (int i = 0; i < 2; i++) {
                int ro = (wm * 32 + i * 16) * LDA + ks * 16;
                wmma::load_matrix_sync(ah[i], &Ah[ro], LDA);
                wmma::load_matrix_sync(al[i], &Al[ro], LDA);
            }
#pragma unroll
            for (int j = 0; j < 4; j++) {
                wmma::fragment<wmma::matrix_b, 16, 16, 16, __nv_bfloat16, wmma::col_major> bh, bl;
                int ro = (wn * 64 + j * 16) * LDA + ks * 16;
                wmma::load_matrix_sync(bh, &Bh[ro], LDA);
                wmma::load_matrix_sync(bl, &Bl[ro], LDA);
#pragma unroll
                for (int i = 0; i < 2; i++) {
                    wmma::mma_sync(acc[i][j], ah[i], bh, acc[i][j]);
                    wmma::mma_sync(acc[i][j], ah[i], bl, acc[i][j]);
                    wmma::mma_sync(acc[i][j], al[i], bh, acc[i][j]);
                }
            }
        }
    }

    // stores unguarded into padded g_h (MPAD rows)
#pragma unroll
    for (int i = 0; i < 2; i++)
#pragma unroll
        for (int j = 0; j < 4; j++)
            wmma::store_matrix_sync(
                &g_h[(size_t)(m0 + wm * 32 + 16 * i) * HF_ + n0 + wn * 64 + 16 * j],
                acc[i][j], HF_, wmma::mem_row_major);

    // ---- fused score epilogue: block-scope visibility of our own g_h stores
    __syncthreads();
    {
        const int r = tid >> 1;               // 0..127
        const int half = tid & 1;             // 0..1
        const int row = m0 + r;
        if (row < M) {
            const int c0 = n0 + half * 64;    // 2 heads' columns
            const int hbase = c0 >> 5;        // first head index
            const float* hp = &g_h[(size_t)row * HF_ + c0];
            float s0 = 0.f, d0 = 0.f, s1 = 0.f, d1 = 0.f;
#pragma unroll
            for (int q = 0; q < 8; q++) {
                float4 hv0 = *(const float4*)&hp[q * 4];
                float4 hv1 = *(const float4*)&hp[32 + q * 4];
                float4 a0 = *(const float4*)&a_src[hbase * 32 + q * 4];
                float4 b0 = *(const float4*)&a_dst[hbase * 32 + q * 4];
                float4 a1 = *(const float4*)&a_src[(hbase + 1) * 32 + q * 4];
                float4 b1 = *(const float4*)&a_dst[(hbase + 1) * 32 + q * 4];
                s0 += hv0.x * a0.x + hv0.y * a0.y + hv0.z * a0.z + hv0.w * a0.w;
                d0 += hv0.x * b0.x + hv0.y * b0.y + hv0.z * b0.z + hv0.w * b0.w;
                s1 += hv1.x * a1.x + hv1.y * a1.y + hv1.z * a1.z + hv1.w * a1.w;
                d1 += hv1.x * b1.x + hv1.y * b1.y + hv1.z * b1.z + hv1.w * b1.w;
            }
            g_ssrc[row * HEADS_ + hbase] = s0;
            g_ssrc[row * HEADS_ + hbase + 1] = s1;
            g_sdst[row * HEADS_ + hbase] = d0;
            g_sdst[row * HEADS_ + hbase + 1] = d1;
        }
    }
}

// ---------------- CSR build --------------------------------------------------
__global__ void k_count(const int* __restrict__ dst, int E) {
    int e = blockIdx.x * blockDim.x + threadIdx.x;
    if (e < E) atomicAdd(&g_deg[dst[e]], 1);
}

// single-block shfl scan, 4 elements per thread -> g_rowstart
__global__ void k_scan(int NN) {
    __shared__ int warpsum[32];
    __shared__ int carry;
    const int tid = threadIdx.x;
    const int lane = tid & 31;
    const int wid = tid >> 5;
    if (tid == 0) carry = 0;
    __syncthreads();
    for (int base = 0; base < NN; base += 4096) {
        int i0 = base + tid * 4;
        int v0 = (i0 + 0 < NN) ? g_deg[i0 + 0] : 0;
        int v1 = (i0 + 1 < NN) ? g_deg[i0 + 1] : 0;
        int v2 = (i0 + 2 < NN) ? g_deg[i0 + 2] : 0;
        int v3 = (i0 + 3 < NN) ? g_deg[i0 + 3] : 0;
        int tsum = v0 + v1 + v2 + v3;
        int s = tsum;
#pragma unroll
        for (int o = 1; o < 32; o <<= 1) {
            int t = __shfl_up_sync(0xffffffffu, s, o);
            if (lane >= o) s += t;
        }
        if (lane == 31) warpsum[wid] = s;
        __syncthreads();
        if (wid == 0) {
            int ws = warpsum[lane];
#pragma unroll
            for (int o = 1; o < 32; o <<= 1) {
                int t = __shfl_up_sync(0xffffffffu, ws, o);
                if (lane >= o) ws += t;
            }
            warpsum[lane] = ws;
        }
        __syncthreads();
        int excl = s - tsum + (wid > 0 ? warpsum[wid - 1] : 0) + carry;
        if (i0 + 0 < NN) g_rowstart[i0 + 0] = excl; excl += v0;
        if (i0 + 1 < NN) g_rowstart[i0 + 1] = excl; excl += v1;
        if (i0 + 2 < NN) g_rowstart[i0 + 2] = excl; excl += v2;
        if (i0 + 3 < NN) g_rowstart[i0 + 3] = excl;
        int total = warpsum[31];
        __syncthreads();
        if (tid == 0) carry += total;
        __syncthreads();
    }
    if (tid == 0) g_rowstart[NN] = carry;
}

__global__ void k_fill(const int* __restrict__ src, const int* __restrict__ dst, int E) {
    int e = blockIdx.x * blockDim.x + threadIdx.x;
    if (e >= E) return;
    int d = dst[e];
    int pos = atomicAdd(&g_cursor[d], 1);
    g_csr_src[g_rowstart[d] + pos] = src[e];
}

// ---------------- fused single-pass softmax + aggregation --------------------
// WARP PER NODE. Lane q owns float4 columns q and q+32 of the node's 256-float
// output row, i.e. head h0=q>>3 and head h1=h0+4. Per edge: whole 1KB h-row as
// 2 coalesced LDG.128/lane, scores as 2 broadcast 4B loads (one 32B sector),
// only 2 exp instructions per warp-edge (vs 8 in warp-per-head). wsum needs no
// reduction: all 8 lanes of a head compute identical sums.
__global__ void __launch_bounds__(256) k_aggr(float* __restrict__ out, int NN) {
    const int w = (blockIdx.x * blockDim.x + threadIdx.x) >> 5;  // node
    if (w >= NN) return;
    const int lane = threadIdx.x & 31;
    const int h0 = lane >> 3;            // head of first float4
    const int rs = g_rowstart[w];
    const int re = g_rowstart[w + 1];
    const float sd0 = g_sdst[w * HEADS_ + h0];
    const float sd1 = g_sdst[w * HEADS_ + h0 + 4];

    float4 acc0 = make_float4(0.f, 0.f, 0.f, 0.f);
    float4 acc1 = make_float4(0.f, 0.f, 0.f, 0.f);
    float ws0 = 0.f, ws1 = 0.f;

    int i = rs;
    for (; i + 4 <= re; i += 4) {
        int sn[4];
        float4 hv0[4], hv1[4];
        float sa[4], sb[4];
#pragma unroll
        for (int q = 0; q < 4; q++) sn[q] = g_csr_src[i + q];
#pragma unroll
        for (int q = 0; q < 4; q++) {
            const float4* hp = (const float4*)&g_h[(size_t)sn[q] * HF_];
            hv0[q] = hp[lane];
            hv1[q] = hp[lane + 32];
        }
#pragma unroll
        for (int q = 0; q < 4; q++) {
            sa[q] = g_ssrc[sn[q] * HEADS_ + h0];
            sb[q] = g_ssrc[sn[q] * HEADS_ + h0 + 4];
        }
#pragma unroll
        for (int q = 0; q < 4; q++) {
            float a0 = sa[q] + sd0;
            float a1 = sb[q] + sd1;
            a0 = a0 > 0.f ? a0 : 0.2f * a0;
            a1 = a1 > 0.f ? a1 : 0.2f * a1;
            float e0 = __expf(a0);
            float e1 = __expf(a1);
            ws0 += e0; ws1 += e1;
            acc0.x = fmaf(e0, hv0[q].x, acc0.x);
            acc0.y = fmaf(e0, hv0[q].y, acc0.y);
            acc0.z = fmaf(e0, hv0[q].z, acc0.z);
            acc0.w = fmaf(e0, hv0[q].w, acc0.w);
            acc1.x = fmaf(e1, hv1[q].x, acc1.x);
            acc1.y = fmaf(e1, hv1[q].y, acc1.y);
            acc1.z = fmaf(e1, hv1[q].z, acc1.z);
            acc1.w = fmaf(e1, hv1[q].w, acc1.w);
        }
    }
    for (; i < re; i++) {
        int s = g_csr_src[i];
        const float4* hp = (const float4*)&g_h[(size_t)s * HF_];
        float4 hv0 = hp[lane];
        float4 hv1 = hp[lane + 32];
        float a0 = g_ssrc[s * HEADS_ + h0] + sd0;
        float a1 = g_ssrc[s * HEADS_ + h0 + 4] + sd1;
        a0 = a0 > 0.f ? a0 : 0.2f * a0;
        a1 = a1 > 0.f ? a1 : 0.2f * a1;
        float e0 = __expf(a0);
        float e1 = __expf(a1);
        ws0 += e0; ws1 += e1;
        acc0.x = fmaf(e0, hv0.x, acc0.x);
        acc0.y = fmaf(e0, hv0.y, acc0.y);
        acc0.z = fmaf(e0, hv0.z, acc0.z);
        acc0.w = fmaf(e0, hv0.w, acc0.w);
        acc1.x = fmaf(e1, hv1.x, acc1.x);
        acc1.y = fmaf(e1, hv1.y, acc1.y);
        acc1.z = fmaf(e1, hv1.z, acc1.z);
        acc1.w = fmaf(e1, hv1.w, acc1.w);
    }

    const float i0 = 1.0f / (ws0 + 1e-8f);
    const float i1 = 1.0f / (ws1 + 1e-8f);
    float4* op = (float4*)&out[(size_t)w * HF_];
    op[lane]      = make_float4(acc0.x * i0, acc0.y * i0, acc0.z * i0, acc0.w * i0);
    op[lane + 32] = make_float4(acc1.x * i1, acc1.y * i1, acc1.z * i1, acc1.w * i1);
}

// ---------------- launch -----------------------------------------------------
extern "C" void kernel_launch(void* const* d_in, const int* in_sizes, int n_in,
                              void* d_out, int out_size) {
    const float* x     = (const float*)d_in[0];
    const int*   ei    = (const int*)d_in[1];
    const float* W     = (const float*)d_in[2];
    const float* a_src = (const float*)d_in[3];
    const float* a_dst = (const float*)d_in[4];
    float* out = (float*)d_out;

    const int M = in_sizes[0] / INF_;     // 50000
    const int E = in_sizes[1] / 2;        // 800000
    const int* src = ei;
    const int* dst = ei + E;

    const int mblocks = (M + 127) / 128;  // 391; mblocks*128 <= MPAD

    k_wsz<<<(HF_ * INF_ + 255) / 256, 256>>>(W, M);
    k_count<<<(E + 255) / 256, 256>>>(dst, E);
    k_scan<<<1, 1024>>>(M);
    k_gemm_wmma<<<dim3(2, mblocks), 256>>>(x, a_src, a_dst, M);
    k_fill<<<(E + 255) / 256, 256>>>(src, dst, E);
    k_aggr<<<(M * 32 + 255) / 256, 256>>>(out, M);
}